// round 7
// baseline (speedup 1.0000x reference)
#include <cuda_runtime.h>
#include <float.h>

// Fused sRGB->CIELab + per-image L min-max normalization, single kernel,
// cross-CTA per-image sync (8 CTAs/image).
//  phase1: read own 2048 px ONCE, gamma+matrix+cbrt+a/b (ALL heavy math),
//          stash (a01,b01,fy) in smem, track fy min/max (monotonic in Y),
//          publish partial, arrive on per-image counter.
//  spin  : thread0 acquire-spins until all 8 partials landed; computes fmin,sf.
//  phase2: trivial: L=(fy-fmin)*sf, reassemble, coalesced streaming stores.
// Counters self-reset via a done-counter (no memset node). DRAM = 1R + 1W.

#define NPIX    16384
#define NIMG    512
#define SUBS    8
#define THREADS 256
#define PX_CTA  (NPIX / SUBS)          // 2048
#define NG_CTA  (PX_CTA / 4)           // 512 groups of 4 px
#define GROUPS  (NG_CTA / THREADS)     // 2 per thread

__device__ float g_pmin[NIMG * SUBS];
__device__ float g_pmax[NIMG * SUBS];
__device__ int   g_arrive[NIMG];       // zero-init; self-reset each launch
__device__ int   g_done[NIMG];         // zero-init; self-reset each launch

__device__ __forceinline__ float mufu_lg2(float x) {
    float r; asm("lg2.approx.f32 %0, %1;" : "=f"(r) : "f"(x)); return r;
}
__device__ __forceinline__ float mufu_ex2(float x) {
    float r; asm("ex2.approx.f32 %0, %1;" : "=f"(r) : "f"(x)); return r;
}
__device__ __forceinline__ float mufu_rcp(float x) {
    float r; asm("rcp.approx.f32 %0, %1;" : "=f"(r) : "f"(x)); return r;
}

__device__ __forceinline__ float srgb_lin(float c) {
    float t = fmaf(c, 1.0f / 1.055f, 0.055f / 1.055f);
    float p = mufu_ex2(2.4f * mufu_lg2(t));
    return (c > 0.04045f) ? p : c * (1.0f / 12.92f);
}

__device__ __forceinline__ float xyz_f(float t) {
    float cr = mufu_ex2((1.0f / 3.0f) * mufu_lg2(t));
    return (t > 0.008856f) ? cr : fmaf(t, 7.787f, 16.0f / 116.0f);
}

// full per-pixel Lab math except L-normalization
__device__ __forceinline__ void lab_pre(float r, float g, float b,
                                        float& fy_o, float& a01, float& b01) {
    float rl = srgb_lin(r);
    float gl = srgb_lin(g);
    float bl = srgb_lin(b);
    const float M00 = 0.412453f / 0.95047f, M01 = 0.357580f / 0.95047f, M02 = 0.180423f / 0.95047f;
    const float M10 = 0.212671f,            M11 = 0.715160f,            M12 = 0.072169f;
    const float M20 = 0.019334f / 1.08883f, M21 = 0.119193f / 1.08883f, M22 = 0.950227f / 1.08883f;
    float X = fmaf(M00, rl, fmaf(M01, gl, M02 * bl));
    float Y = fmaf(M10, rl, fmaf(M11, gl, M12 * bl));
    float Z = fmaf(M20, rl, fmaf(M21, gl, M22 * bl));
    float fx = xyz_f(X);
    float fy = xyz_f(Y);
    float fz = xyz_f(Z);
    fy_o = fy;
    a01 = fmaf(fx - fy, 500.0f / 255.0f, 128.0f / 255.0f);
    b01 = fmaf(fy - fz, 200.0f / 255.0f, 128.0f / 255.0f);
}

__global__ void __launch_bounds__(THREADS, 6)
rgb2lab_sync_kernel(const float* __restrict__ x, float* __restrict__ out) {
    __shared__ float4 sA[NG_CTA];      // 8KB  a01 plane
    __shared__ float4 sB[NG_CTA];      // 8KB  b01 plane
    __shared__ float4 sF[NG_CTA];      // 8KB  fy plane
    __shared__ float  red[18];

    const int bid = blockIdx.x;
    const int img = bid >> 3;
    const int tid = threadIdx.x;

    const int base4 = bid * (PX_CTA * 3 / 4);   // contiguous in bid
    const float4* in4 = (const float4*)x   + base4;
    float4*       o4  = (float4*)      out + base4;

    float fmn = FLT_MAX, fmx = -FLT_MAX;

    // ---------------- phase 1: ALL heavy math, stash (a,b,fy) -------------
    #pragma unroll
    for (int j = 0; j < GROUPS; j++) {
        int gi = tid + j * THREADS;
        float4 v0 = __ldcs(&in4[gi * 3 + 0]);
        float4 v1 = __ldcs(&in4[gi * 3 + 1]);
        float4 v2 = __ldcs(&in4[gi * 3 + 2]);

        float4 f4, a4, b4;
        lab_pre(v0.x, v0.y, v0.z, f4.x, a4.x, b4.x);
        lab_pre(v0.w, v1.x, v1.y, f4.y, a4.y, b4.y);
        lab_pre(v1.z, v1.w, v2.x, f4.z, a4.z, b4.z);
        lab_pre(v2.y, v2.z, v2.w, f4.w, a4.w, b4.w);

        sA[gi] = a4;  sB[gi] = b4;  sF[gi] = f4;

        fmn = fminf(fminf(fminf(fmn, f4.x), fminf(f4.y, f4.z)), f4.w);
        fmx = fmaxf(fmaxf(fmaxf(fmx, f4.x), fmaxf(f4.y, f4.z)), f4.w);
    }

    // ---------------- CTA-local reduce (8 warps) --------------------------
    #pragma unroll
    for (int off = 16; off > 0; off >>= 1) {
        fmn = fminf(fmn, __shfl_xor_sync(0xffffffffu, fmn, off));
        fmx = fmaxf(fmx, __shfl_xor_sync(0xffffffffu, fmx, off));
    }
    int lane = tid & 31, wid = tid >> 5;
    if (lane == 0) { red[wid] = fmn; red[8 + wid] = fmx; }
    __syncthreads();

    // ---------------- publish partial + spin + self-reset -----------------
    if (tid == 0) {
        float mn = red[0], mx = red[8];
        #pragma unroll
        for (int i = 1; i < 8; i++) {
            mn = fminf(mn, red[i]);
            mx = fmaxf(mx, red[8 + i]);
        }
        g_pmin[bid] = mn;
        g_pmax[bid] = mx;
        asm volatile("red.release.gpu.global.add.s32 [%0], 1;"
                     :: "l"(&g_arrive[img]) : "memory");

        int c;
        do {
            asm volatile("ld.acquire.gpu.global.s32 %0, [%1];"
                         : "=r"(c) : "l"(&g_arrive[img]) : "memory");
            if (c < SUBS) __nanosleep(64);
        } while (c < SUBS);

        float fm = FLT_MAX, fM = -FLT_MAX;
        #pragma unroll
        for (int i = 0; i < SUBS; i++) {
            fm = fminf(fm, g_pmin[img * 8 + i]);
            fM = fmaxf(fM, g_pmax[img * 8 + i]);
        }
        red[16] = fm;
        red[17] = mufu_rcp(fM - fm);

        // self-reset: last CTA past the spin zeroes both counters
        int prev = atomicAdd(&g_done[img], 1);
        if (prev == SUBS - 1) {
            g_arrive[img] = 0;
            g_done[img]   = 0;
        }
    }
    __syncthreads();
    const float fmin = red[16];
    const float sf   = red[17];

    // ---------------- phase 2: trivial normalize + store ------------------
    #pragma unroll
    for (int j = 0; j < GROUPS; j++) {
        int gi = tid + j * THREADS;
        float4 a4 = sA[gi];
        float4 b4 = sB[gi];
        float4 f4 = sF[gi];

        float L0 = (f4.x - fmin) * sf;
        float L1 = (f4.y - fmin) * sf;
        float L2 = (f4.z - fmin) * sf;
        float L3 = (f4.w - fmin) * sf;

        __stcs(&o4[gi * 3 + 0], make_float4(L0,   a4.x, b4.x, L1));
        __stcs(&o4[gi * 3 + 1], make_float4(a4.y, b4.y, L2,   a4.z));
        __stcs(&o4[gi * 3 + 2], make_float4(b4.z, L3,   a4.w, b4.w));
    }
}

extern "C" void kernel_launch(void* const* d_in, const int* in_sizes, int n_in,
                              void* d_out, int out_size) {
    const float* x   = (const float*)d_in[0];
    float*       out = (float*)d_out;

    rgb2lab_sync_kernel<<<NIMG * SUBS, THREADS>>>(x, out);
}